// round 4
// baseline (speedup 1.0000x reference)
#include <cuda_runtime.h>
#include <cstdint>

// Problem constants
#define S_LEN 4096
#define BATCH 4
#define DIM   1024
#define MROWS (BATCH * S_LEN)   // 16384

// -------- scratch (allocation-free: __device__ globals) ------------------
__device__ float g_Q[(size_t)MROWS * DIM];              // 64 MB
__device__ float g_K[(size_t)MROWS * DIM];              // 64 MB
__device__ float g_V[(size_t)MROWS * DIM];              // 64 MB
__device__ float g_S[(size_t)BATCH * S_LEN * S_LEN];    // 256 MB
__device__ float g_C[(size_t)MROWS * DIM];              // 64 MB

// -------- TF32 helpers ----------------------------------------------------
__device__ __forceinline__ uint32_t f2tf32(float x) {
    uint32_t r;
    asm("cvt.rna.tf32.f32 %0, %1;" : "=r"(r) : "f"(x));
    return r;
}

// -------- tiled TF32 GEMM ---------------------------------------------------
// C[M,N] = scale * (A @ opB) + bias
//   BLAYOUT == 0 : B is [N,K] row-major  -> C = A @ B^T   (torch Linear weights)
//   BLAYOUT == 1 : B is [K,N] row-major  -> C = A @ B     (P @ V)
// Tiles: BM=128, BN=128, BK=32, 256 threads (8 warps, 4(M) x 2(N)),
// each warp: 32(M) x 64(N) via m16n8k8 tf32 mma (2 x 8 fragments).
constexpr int BM = 128, BN = 128, BK = 32;

template <int BLAYOUT>
__global__ void __launch_bounds__(256)
gemm_tf32(const float* __restrict__ A, const float* __restrict__ B,
          float* __restrict__ C,
          int M, int N, int K,
          long sA, long sB, long sC,
          const float* __restrict__ bias, float scale)
{
    __shared__ float As[BM][BK + 4];   // stride 36 words -> conflict-free frag loads
    __shared__ float Bs[BK][BN + 4];   // stride 132 words

    A += (long)blockIdx.z * sA;
    B += (long)blockIdx.z * sB;
    C += (long)blockIdx.z * sC;

    const int m0  = blockIdx.y * BM;
    const int n0  = blockIdx.x * BN;
    const int tid = threadIdx.x;
    const int lane = tid & 31;
    const int warp = tid >> 5;
    const int wm = (warp & 3) * 32;    // warp M offset inside CTA tile
    const int wn = (warp >> 2) * 64;   // warp N offset inside CTA tile
    const int g  = lane >> 2;          // groupID   (0..7)
    const int t  = lane & 3;           // tid-in-group (0..3)

    float acc[2][8][4];
#pragma unroll
    for (int i = 0; i < 2; i++)
#pragma unroll
        for (int j = 0; j < 8; j++)
#pragma unroll
            for (int c = 0; c < 4; c++) acc[i][j][c] = 0.f;

    for (int k0 = 0; k0 < K; k0 += BK) {
        // ---- A tile: 128 x 32, coalesced float4 along K -------------------
        {
            const int r  = tid >> 3;          // 0..31
            const int c4 = (tid & 7) * 4;     // 0..28
#pragma unroll
            for (int p = 0; p < 4; p++) {
                const int row = r + p * 32;
                float4 v = *reinterpret_cast<const float4*>(
                    &A[(long)(m0 + row) * K + k0 + c4]);
                As[row][c4 + 0] = __uint_as_float(f2tf32(v.x));
                As[row][c4 + 1] = __uint_as_float(f2tf32(v.y));
                As[row][c4 + 2] = __uint_as_float(f2tf32(v.z));
                As[row][c4 + 3] = __uint_as_float(f2tf32(v.w));
            }
        }
        // ---- B tile -> Bs[k][n] -------------------------------------------
        if (BLAYOUT == 0) {
            // B is [N,K]: transpose into smem, coalesced float4 along K
            const int nr = tid >> 3;
            const int c4 = (tid & 7) * 4;
#pragma unroll
            for (int p = 0; p < 4; p++) {
                const int nn = nr + p * 32;
                float4 v = *reinterpret_cast<const float4*>(
                    &B[(long)(n0 + nn) * K + k0 + c4]);
                Bs[c4 + 0][nn] = __uint_as_float(f2tf32(v.x));
                Bs[c4 + 1][nn] = __uint_as_float(f2tf32(v.y));
                Bs[c4 + 2][nn] = __uint_as_float(f2tf32(v.z));
                Bs[c4 + 3][nn] = __uint_as_float(f2tf32(v.w));
            }
        } else {
            // B is [K,N]: direct copy, coalesced float4 along N
            const int kr = tid >> 5;          // 0..7
            const int c4 = (tid & 31) * 4;    // 0..124
#pragma unroll
            for (int p = 0; p < 4; p++) {
                const int kk = kr + p * 8;
                float4 v = *reinterpret_cast<const float4*>(
                    &B[(long)(k0 + kk) * N + n0 + c4]);
                Bs[kk][c4 + 0] = __uint_as_float(f2tf32(v.x));
                Bs[kk][c4 + 1] = __uint_as_float(f2tf32(v.y));
                Bs[kk][c4 + 2] = __uint_as_float(f2tf32(v.z));
                Bs[kk][c4 + 3] = __uint_as_float(f2tf32(v.w));
            }
        }
        __syncthreads();

        // ---- compute: 4 k-steps of m16n8k8 --------------------------------
#pragma unroll
        for (int kk = 0; kk < BK; kk += 8) {
            uint32_t af[2][4], bf[8][2];
#pragma unroll
            for (int i = 0; i < 2; i++) {
                const int mr = wm + i * 16;
                af[i][0] = __float_as_uint(As[mr + g    ][kk + t    ]);
                af[i][1] = __float_as_uint(As[mr + g + 8][kk + t    ]);
                af[i][2] = __float_as_uint(As[mr + g    ][kk + t + 4]);
                af[i][3] = __float_as_uint(As[mr + g + 8][kk + t + 4]);
            }
#pragma unroll
            for (int j = 0; j < 8; j++) {
                const int nc = wn + j * 8;
                bf[j][0] = __float_as_uint(Bs[kk + t    ][nc + g]);
                bf[j][1] = __float_as_uint(Bs[kk + t + 4][nc + g]);
            }
#pragma unroll
            for (int i = 0; i < 2; i++)
#pragma unroll
                for (int j = 0; j < 8; j++)
                    asm volatile(
                        "mma.sync.aligned.m16n8k8.row.col.f32.tf32.tf32.f32 "
                        "{%0,%1,%2,%3}, {%4,%5,%6,%7}, {%8,%9}, {%0,%1,%2,%3};\n"
                        : "+f"(acc[i][j][0]), "+f"(acc[i][j][1]),
                          "+f"(acc[i][j][2]), "+f"(acc[i][j][3])
                        : "r"(af[i][0]), "r"(af[i][1]),
                          "r"(af[i][2]), "r"(af[i][3]),
                          "r"(bf[j][0]), "r"(bf[j][1]));
        }
        __syncthreads();
    }

    // ---- epilogue: scale + bias ------------------------------------------
#pragma unroll
    for (int i = 0; i < 2; i++) {
        const int row0 = m0 + wm + i * 16 + g;
#pragma unroll
        for (int j = 0; j < 8; j++) {
            const int col = n0 + wn + j * 8 + 2 * t;
            const float b0 = bias ? bias[col]     : 0.f;
            const float b1 = bias ? bias[col + 1] : 0.f;
            C[(long)row0 * N + col]           = acc[i][j][0] * scale + b0;
            C[(long)row0 * N + col + 1]       = acc[i][j][1] * scale + b1;
            C[(long)(row0 + 8) * N + col]     = acc[i][j][2] * scale + b0;
            C[(long)(row0 + 8) * N + col + 1] = acc[i][j][3] * scale + b1;
        }
    }
}

// -------- row softmax (in place), 4096 cols, 1 CTA / row --------------------
__global__ void __launch_bounds__(256)
softmax_rows(float* __restrict__ Sm)
{
    const long row = blockIdx.x;
    float* p = Sm + row * (long)S_LEN;
    const int tid = threadIdx.x;

    float4 v[4];
    float mx = -3.0e38f;
#pragma unroll
    for (int i = 0; i < 4; i++) {
        v[i] = reinterpret_cast<float4*>(p)[tid + i * 256];
        mx = fmaxf(mx, fmaxf(fmaxf(v[i].x, v[i].y), fmaxf(v[i].z, v[i].w)));
    }
    __shared__ float red[8];
#pragma unroll
    for (int o = 16; o > 0; o >>= 1) mx = fmaxf(mx, __shfl_xor_sync(0xffffffffu, mx, o));
    if ((tid & 31) == 0) red[tid >> 5] = mx;
    __syncthreads();
    mx = red[0];
#pragma unroll
    for (int w = 1; w < 8; w++) mx = fmaxf(mx, red[w]);
    __syncthreads();   // red reused below

    float sum = 0.f;
#pragma unroll
    for (int i = 0; i < 4; i++) {
        v[i].x = __expf(v[i].x - mx);
        v[i].y = __expf(v[i].y - mx);
        v[i].z = __expf(v[i].z - mx);
        v[i].w = __expf(v[i].w - mx);
        sum += v[i].x + v[i].y + v[i].z + v[i].w;
    }
#pragma unroll
    for (int o = 16; o > 0; o >>= 1) sum += __shfl_xor_sync(0xffffffffu, sum, o);
    if ((tid & 31) == 0) red[tid >> 5] = sum;
    __syncthreads();
    sum = 0.f;
#pragma unroll
    for (int w = 0; w < 8; w++) sum += red[w];
    const float inv = 1.0f / sum;

#pragma unroll
    for (int i = 0; i < 4; i++) {
        v[i].x *= inv; v[i].y *= inv; v[i].z *= inv; v[i].w *= inv;
        reinterpret_cast<float4*>(p)[tid + i * 256] = v[i];
    }
}

// -------- launch -------------------------------------------------------------
extern "C" void kernel_launch(void* const* d_in, const int* in_sizes, int n_in,
                              void* d_out, int out_size)
{
    const float* x  = (const float*)d_in[0];
    const float* Wq = (const float*)d_in[1];
    const float* bq = (const float*)d_in[2];
    const float* Wk = (const float*)d_in[3];
    const float* bk = (const float*)d_in[4];
    const float* Wv = (const float*)d_in[5];
    const float* bv = (const float*)d_in[6];
    const float* Wo = (const float*)d_in[7];
    const float* bo = (const float*)d_in[8];
    float* out = (float*)d_out;

    float *Q, *Kb, *V, *Sm, *Cx;
    cudaGetSymbolAddress((void**)&Q,  g_Q);
    cudaGetSymbolAddress((void**)&Kb, g_K);
    cudaGetSymbolAddress((void**)&V,  g_V);
    cudaGetSymbolAddress((void**)&Sm, g_S);
    cudaGetSymbolAddress((void**)&Cx, g_C);

    dim3 blk(256);

    // 1) QKV projections: [16384,1024] @ [1024,1024]^T + bias
    dim3 gq(DIM / BN, MROWS / BM, 1);
    gemm_tf32<0><<<gq, blk>>>(x, Wq, Q,  MROWS, DIM, DIM, 0, 0, 0, bq, 1.f);
    gemm_tf32<0><<<gq, blk>>>(x, Wk, Kb, MROWS, DIM, DIM, 0, 0, 0, bk, 1.f);
    gemm_tf32<0><<<gq, blk>>>(x, Wv, V,  MROWS, DIM, DIM, 0, 0, 0, bv, 1.f);

    // 2) scores = Q @ K^T / 32, batched over 4
    dim3 gs(S_LEN / BN, S_LEN / BM, BATCH);
    gemm_tf32<0><<<gs, blk>>>(Q, Kb, Sm, S_LEN, S_LEN, DIM,
                              (long)S_LEN * DIM, (long)S_LEN * DIM,
                              (long)S_LEN * S_LEN, nullptr, 0.03125f);

    // 3) row softmax over 16384 rows of 4096
    softmax_rows<<<MROWS, 256>>>(Sm);

    // 4) ctx = P @ V, batched over 4 (B row-major)
    dim3 gc(DIM / BN, S_LEN / BM, BATCH);
    gemm_tf32<1><<<gc, blk>>>(Sm, V, Cx, S_LEN, DIM, S_LEN,
                              (long)S_LEN * S_LEN, (long)S_LEN * DIM,
                              (long)S_LEN * DIM, nullptr, 1.f);

    // 5) out = ctx @ Wo^T + bo
    gemm_tf32<0><<<gq, blk>>>(Cx, Wo, out, MROWS, DIM, DIM, 0, 0, 0, bo, 1.f);
}

// round 5
// speedup vs baseline: 2.0861x; 2.0861x over previous
#include <cuda_runtime.h>
#include <cuda_fp16.h>
#include <cstdint>

#define S_LEN 4096
#define BATCH 4
#define DIM   1024
#define MROWS (BATCH * S_LEN)   // 16384

// ---------------- scratch (allocation-free __device__ globals, fp16) --------
__device__ __half g_xh[(size_t)MROWS * DIM];
__device__ __half g_wq[(size_t)DIM * DIM];
__device__ __half g_wk[(size_t)DIM * DIM];
__device__ __half g_wv[(size_t)DIM * DIM];
__device__ __half g_wo[(size_t)DIM * DIM];
__device__ __half g_Qh[(size_t)MROWS * DIM];
__device__ __half g_Kh[(size_t)MROWS * DIM];
__device__ __half g_Vh[(size_t)MROWS * DIM];
__device__ __half g_Sh[(size_t)BATCH * S_LEN * S_LEN];
__device__ __half g_Ch[(size_t)MROWS * DIM];

// ---------------- fp32 -> fp16 converter ------------------------------------
__global__ void __launch_bounds__(256)
cvt_f2h(const float* __restrict__ in, __half* __restrict__ out)
{
    const long i = ((long)blockIdx.x * 256 + threadIdx.x) * 4;
    float4 v = *reinterpret_cast<const float4*>(in + i);
    __half2* o = reinterpret_cast<__half2*>(out + i);
    o[0] = __floats2half2_rn(v.x, v.y);
    o[1] = __floats2half2_rn(v.z, v.w);
}

// ---------------- fp16 GEMM --------------------------------------------------
// C[M,N] = scale * (A @ opB) + bias
//   BLAYOUT==0 : B is [N,K] row-major -> C = A @ B^T   (smem Bs[n][k], ldmatrix)
//   BLAYOUT==1 : B is [K,N] row-major -> C = A @ B     (smem Bs[k][n], ldmatrix.trans)
// BM=128, BN=256, BK=32; 256 threads = 8 warps (2M x 4N), warp tile 64x64,
// m16n8k16 HMMA, fp32 accumulate, cp.async double buffering.
constexpr int BM = 128, BN = 256, BK = 32;
constexpr int AST = 40;    // As stride (halves): 32 + 8 pad
constexpr int B0ST = 40;   // Bs stride, layout0 [n][k]
constexpr int B1ST = 264;  // Bs stride, layout1 [k][n]: 256 + 8 pad
constexpr int ASTG = BM * AST;      // 5120 halves / stage
constexpr int BSTG = BN * B0ST;     // 10240 halves / stage (>= 32*264=8448)
constexpr int SMEM_BYTES = 2 * (ASTG + BSTG) * 2;   // 61440 B

__device__ __forceinline__ uint32_t s2u(const void* p) {
    uint32_t a;
    asm("{ .reg .u64 t; cvta.to.shared.u64 t, %1; cvt.u32.u64 %0, t; }"
        : "=r"(a) : "l"(p));
    return a;
}
__device__ __forceinline__ void cp16(uint32_t s, const void* g) {
    asm volatile("cp.async.cg.shared.global [%0], [%1], 16;\n" :: "r"(s), "l"(g));
}

template<int BLAYOUT>
__device__ __forceinline__ void load_tile(
    const __half* __restrict__ A, const __half* __restrict__ B,
    int K, int N, int m0, int n0, int tid,
    uint32_t as_u, uint32_t bs_u, int buf, int k0)
{
#pragma unroll
    for (int p = 0; p < 2; p++) {                 // A: 128x32 halves = 512 x 16B
        const int c = tid + p * 256;
        const int row = c >> 2, k8 = (c & 3) * 8;
        cp16(as_u + (buf * ASTG + row * AST + k8) * 2,
             A + (long)(m0 + row) * K + k0 + k8);
    }
#pragma unroll
    for (int p = 0; p < 4; p++) {                 // B: 1024 x 16B
        const int c = tid + p * 256;
        if (BLAYOUT == 0) {
            const int row = c >> 2, k8 = (c & 3) * 8;
            cp16(bs_u + (buf * BSTG + row * B0ST + k8) * 2,
                 B + (long)(n0 + row) * K + k0 + k8);
        } else {
            const int row = c >> 5, n8 = (c & 31) * 8;
            cp16(bs_u + (buf * BSTG + row * B1ST + n8) * 2,
                 B + (long)(k0 + row) * N + n0 + n8);
        }
    }
}

template<int BLAYOUT, int OUTF32>
__global__ void __launch_bounds__(256, 1)
hgemm(const __half* __restrict__ A, const __half* __restrict__ B,
      void* __restrict__ Cv,
      int M, int N, int K, long sA, long sB, long sC,
      const float* __restrict__ bias, float scale)
{
    extern __shared__ __half sm[];
    const uint32_t as_u = s2u(sm);
    const uint32_t bs_u = s2u(sm + 2 * ASTG);

    A += (long)blockIdx.z * sA;
    B += (long)blockIdx.z * sB;

    const int m0 = blockIdx.y * BM;
    const int n0 = blockIdx.x * BN;
    const int tid = threadIdx.x;
    const int lane = tid & 31;
    const int warp = tid >> 5;
    const int wm = (warp & 1) * 64;
    const int wn = (warp >> 1) * 64;

    // ldmatrix per-lane address bases (in halves)
    const int lhi = lane >> 4;                       // 0/1
    const int a_off = (wm + (lane & 15)) * AST + lhi * 8;
    int b_off;
    if (BLAYOUT == 0)
        b_off = (wn + (lane & 7) + lhi * 8) * B0ST + ((lane >> 3) & 1) * 8;
    else
        b_off = (((lane >> 3) & 1) * 8 + (lane & 7)) * B1ST + wn + lhi * 8;

    float acc[4][8][4];
#pragma unroll
    for (int i = 0; i < 4; i++)
#pragma unroll
        for (int j = 0; j < 8; j++)
#pragma unroll
            for (int c = 0; c < 4; c++) acc[i][j][c] = 0.f;

    load_tile<BLAYOUT>(A, B, K, N, m0, n0, tid, as_u, bs_u, 0, 0);
    asm volatile("cp.async.commit_group;\n");

    const int nt = K / BK;
    for (int t = 0; t < nt; t++) {
        const int buf = t & 1;
        if (t + 1 < nt) {
            load_tile<BLAYOUT>(A, B, K, N, m0, n0, tid, as_u, bs_u, buf ^ 1, (t + 1) * BK);
            asm volatile("cp.async.commit_group;\n");
            asm volatile("cp.async.wait_group 1;\n");
        } else {
            asm volatile("cp.async.wait_group 0;\n");
        }
        __syncthreads();

#pragma unroll
        for (int kk = 0; kk < BK; kk += 16) {
            uint32_t a[4][4];
#pragma unroll
            for (int i = 0; i < 4; i++) {
                const uint32_t addr =
                    as_u + (buf * ASTG + a_off + i * (16 * AST) + kk) * 2;
                asm volatile(
                    "ldmatrix.sync.aligned.m8n8.x4.shared.b16 {%0,%1,%2,%3}, [%4];"
                    : "=r"(a[i][0]), "=r"(a[i][1]), "=r"(a[i][2]), "=r"(a[i][3])
                    : "r"(addr));
            }
            uint32_t b[8][2];
#pragma unroll
            for (int jp = 0; jp < 4; jp++) {
                if (BLAYOUT == 0) {
                    const uint32_t addr =
                        bs_u + (buf * BSTG + b_off + jp * (16 * B0ST) + kk) * 2;
                    asm volatile(
                        "ldmatrix.sync.aligned.m8n8.x4.shared.b16 {%0,%1,%2,%3}, [%4];"
                        : "=r"(b[2*jp][0]), "=r"(b[2*jp][1]),
                          "=r"(b[2*jp+1][0]), "=r"(b[2*jp+1][1])
                        : "r"(addr));
                } else {
                    const uint32_t addr =
                        bs_u + (buf * BSTG + b_off + jp * 16 + kk * B1ST) * 2;
                    asm volatile(
                        "ldmatrix.sync.aligned.m8n8.x4.trans.shared.b16 {%0,%1,%2,%3}, [%4];"
                        : "=r"(b[2*jp][0]), "=r"(b[2*jp][1]),
                          "=r"(b[2*jp+1][0]), "=r"(b[2*jp+1][1])
                        : "r"(addr));
                }
            }
#pragma unroll
            for (int i = 0; i < 4; i++)
#pragma unroll
                for (int j = 0; j < 8; j++)
                    asm volatile(
                        "mma.sync.aligned.m16n8k16.row.col.f32.f16.f16.f32 "
                        "{%0,%1,%2,%3}, {%4,%5,%6,%7}, {%8,%9}, {%0,%1,%2,%3};\n"
                        : "+f"(acc[i][j][0]), "+f"(acc[i][j][1]),
                          "+f"(acc[i][j][2]), "+f"(acc[i][j][3])
                        : "r"(a[i][0]), "r"(a[i][1]), "r"(a[i][2]), "r"(a[i][3]),
                          "r"(b[j][0]), "r"(b[j][1]));
        }
        __syncthreads();
    }

    // ---- epilogue ----
    const int g = lane >> 2, tq = lane & 3;
#pragma unroll
    for (int i = 0; i < 4; i++) {
        const int r0 = m0 + wm + i * 16 + g;
#pragma unroll
        for (int j = 0; j < 8; j++) {
            const int col = n0 + wn + j * 8 + 2 * tq;
            float b0 = 0.f, b1 = 0.f;
            if (bias) { b0 = bias[col]; b1 = bias[col + 1]; }
            const float c0 = acc[i][j][0] * scale + b0;
            const float c1 = acc[i][j][1] * scale + b1;
            const float c2 = acc[i][j][2] * scale + b0;
            const float c3 = acc[i][j][3] * scale + b1;
            if (OUTF32) {
                float* C = (float*)Cv + (long)blockIdx.z * sC;
                *reinterpret_cast<float2*>(C + (long)r0 * N + col) = make_float2(c0, c1);
                *reinterpret_cast<float2*>(C + (long)(r0 + 8) * N + col) = make_float2(c2, c3);
            } else {
                __half* C = (__half*)Cv + (long)blockIdx.z * sC;
                *reinterpret_cast<__half2*>(C + (long)r0 * N + col) = __floats2half2_rn(c0, c1);
                *reinterpret_cast<__half2*>(C + (long)(r0 + 8) * N + col) = __floats2half2_rn(c2, c3);
            }
        }
    }
}

// ---------------- fp16 in-place row softmax (fp32 math) ---------------------
__global__ void __launch_bounds__(256)
softmax_h(__half* __restrict__ Sm)
{
    const long row = blockIdx.x;
    __half* p = Sm + row * (long)S_LEN;
    const int tid = threadIdx.x;

    uint4 u0 = reinterpret_cast<uint4*>(p)[tid];
    uint4 u1 = reinterpret_cast<uint4*>(p)[tid + 256];
    uint32_t w[8] = {u0.x, u0.y, u0.z, u0.w, u1.x, u1.y, u1.z, u1.w};
    float f[16];
    float mx = -3.0e38f;
#pragma unroll
    for (int i = 0; i < 8; i++) {
        float2 v = __half22float2(*reinterpret_cast<__half2*>(&w[i]));
        f[2*i] = v.x; f[2*i+1] = v.y;
        mx = fmaxf(mx, fmaxf(v.x, v.y));
    }
    __shared__ float red[8];
#pragma unroll
    for (int o = 16; o; o >>= 1) mx = fmaxf(mx, __shfl_xor_sync(0xffffffffu, mx, o));
    if ((tid & 31) == 0) red[tid >> 5] = mx;
    __syncthreads();
    mx = red[0];
#pragma unroll
    for (int k = 1; k < 8; k++) mx = fmaxf(mx, red[k]);
    __syncthreads();

    float sum = 0.f;
#pragma unroll
    for (int i = 0; i < 16; i++) { f[i] = __expf(f[i] - mx); sum += f[i]; }
#pragma unroll
    for (int o = 16; o; o >>= 1) sum += __shfl_xor_sync(0xffffffffu, sum, o);
    if ((tid & 31) == 0) red[tid >> 5] = sum;
    __syncthreads();
    sum = 0.f;
#pragma unroll
    for (int k = 0; k < 8; k++) sum += red[k];
    const float inv = 1.0f / sum;

#pragma unroll
    for (int i = 0; i < 8; i++)
        *reinterpret_cast<__half2*>(&w[i]) = __floats2half2_rn(f[2*i] * inv, f[2*i+1] * inv);
    reinterpret_cast<uint4*>(p)[tid]       = make_uint4(w[0], w[1], w[2], w[3]);
    reinterpret_cast<uint4*>(p)[tid + 256] = make_uint4(w[4], w[5], w[6], w[7]);
}

// ---------------- launch ------------------------------------------------------
extern "C" void kernel_launch(void* const* d_in, const int* in_sizes, int n_in,
                              void* d_out, int out_size)
{
    const float* x  = (const float*)d_in[0];
    const float* Wq = (const float*)d_in[1];
    const float* bq = (const float*)d_in[2];
    const float* Wk = (const float*)d_in[3];
    const float* bk = (const float*)d_in[4];
    const float* Wv = (const float*)d_in[5];
    const float* bv = (const float*)d_in[6];
    const float* Wo = (const float*)d_in[7];
    const float* bo = (const float*)d_in[8];
    float* out = (float*)d_out;

    __half *xh, *wq, *wk, *wv, *wo, *Qh, *Kh, *Vh, *Sh, *Ch;
    cudaGetSymbolAddress((void**)&xh, g_xh);
    cudaGetSymbolAddress((void**)&wq, g_wq);
    cudaGetSymbolAddress((void**)&wk, g_wk);
    cudaGetSymbolAddress((void**)&wv, g_wv);
    cudaGetSymbolAddress((void**)&wo, g_wo);
    cudaGetSymbolAddress((void**)&Qh, g_Qh);
    cudaGetSymbolAddress((void**)&Kh, g_Kh);
    cudaGetSymbolAddress((void**)&Vh, g_Vh);
    cudaGetSymbolAddress((void**)&Sh, g_Sh);
    cudaGetSymbolAddress((void**)&Ch, g_Ch);

    cudaFuncSetAttribute(hgemm<0,0>, cudaFuncAttributeMaxDynamicSharedMemorySize, SMEM_BYTES);
    cudaFuncSetAttribute(hgemm<1,0>, cudaFuncAttributeMaxDynamicSharedMemorySize, SMEM_BYTES);
    cudaFuncSetAttribute(hgemm<0,1>, cudaFuncAttributeMaxDynamicSharedMemorySize, SMEM_BYTES);

    dim3 blk(256);

    // 0) fp32 -> fp16 conversions
    cvt_f2h<<<(MROWS * DIM) / 1024, blk>>>(x,  xh);
    cvt_f2h<<<(DIM * DIM)   / 1024, blk>>>(Wq, wq);
    cvt_f2h<<<(DIM * DIM)   / 1024, blk>>>(Wk, wk);
    cvt_f2h<<<(DIM * DIM)   / 1024, blk>>>(Wv, wv);
    cvt_f2h<<<(DIM * DIM)   / 1024, blk>>>(Wo, wo);

    // 1) QKV projections
    dim3 gq(DIM / BN, MROWS / BM, 1);
    hgemm<0,0><<<gq, blk, SMEM_BYTES>>>(xh, wq, Qh, MROWS, DIM, DIM, 0, 0, 0, bq, 1.f);
    hgemm<0,0><<<gq, blk, SMEM_BYTES>>>(xh, wk, Kh, MROWS, DIM, DIM, 0, 0, 0, bk, 1.f);
    hgemm<0,0><<<gq, blk, SMEM_BYTES>>>(xh, wv, Vh, MROWS, DIM, DIM, 0, 0, 0, bv, 1.f);

    // 2) scores = Q @ K^T / 32
    dim3 gs(S_LEN / BN, S_LEN / BM, BATCH);
    hgemm<0,0><<<gs, blk, SMEM_BYTES>>>(Qh, Kh, Sh, S_LEN, S_LEN, DIM,
                                        (long)S_LEN * DIM, (long)S_LEN * DIM,
                                        (long)S_LEN * S_LEN, nullptr, 0.03125f);

    // 3) softmax
    softmax_h<<<MROWS, blk>>>(Sh);

    // 4) ctx = P @ V
    dim3 gc(DIM / BN, S_LEN / BM, BATCH);
    hgemm<1,0><<<gc, blk, SMEM_BYTES>>>(Sh, Vh, Ch, S_LEN, DIM, S_LEN,
                                        (long)S_LEN * S_LEN, (long)S_LEN * DIM,
                                        (long)S_LEN * DIM, nullptr, 1.f);

    // 5) out = ctx @ Wo^T + bo
    hgemm<0,1><<<gq, blk, SMEM_BYTES>>>(Ch, wo, out, MROWS, DIM, DIM, 0, 0, 0, bo, 1.f);
}

// round 9
// speedup vs baseline: 2.3590x; 1.1308x over previous
#include <cuda_runtime.h>
#include <cuda_fp16.h>
#include <cstdint>

#define S_LEN 4096
#define BATCH 4
#define DIM   1024
#define MROWS (BATCH * S_LEN)   // 16384

// ---------------- scratch (allocation-free __device__ globals, fp16) --------
__device__ __half g_xh[(size_t)MROWS * DIM];
__device__ __half g_wq[(size_t)DIM * DIM];
__device__ __half g_wk[(size_t)DIM * DIM];
__device__ __half g_wv[(size_t)DIM * DIM];
__device__ __half g_wo[(size_t)DIM * DIM];
__device__ __half g_Qh[(size_t)MROWS * DIM];
__device__ __half g_Kh[(size_t)MROWS * DIM];
__device__ __half g_Vh[(size_t)MROWS * DIM];
__device__ __half g_Sh[(size_t)BATCH * S_LEN * S_LEN];
__device__ __half g_Ch[(size_t)MROWS * DIM];

// ---------------- fp32 -> fp16 converter ------------------------------------
__global__ void __launch_bounds__(256)
cvt_f2h(const float* __restrict__ in, __half* __restrict__ out)
{
    const long i = ((long)blockIdx.x * 256 + threadIdx.x) * 4;
    float4 v = *reinterpret_cast<const float4*>(in + i);
    __half2* o = reinterpret_cast<__half2*>(out + i);
    o[0] = __floats2half2_rn(v.x, v.y);
    o[1] = __floats2half2_rn(v.z, v.w);
}

// ---------------- fp16 GEMM --------------------------------------------------
// C[M,N] = scale * (A @ opB) + bias
//   BLAYOUT==0 : B is [N,K] row-major -> C = A @ B^T
//   BLAYOUT==1 : B is [K,N] row-major -> C = A @ B     (ldmatrix.trans)
// BM=128, BN=256, BK=64; 512 threads = 16 warps (4M x 4N), warp tile 32x64,
// m16n8k16 HMMA fp32-acc, cp.async 2-stage pipeline.
constexpr int BM = 128, BN = 256, BK = 64;
constexpr int AST  = 72;             // A smem stride (halves): 64 + 8
constexpr int B0ST = 72;             // B smem stride, layout0 [n][k]
constexpr int B1ST = 264;            // B smem stride, layout1 [k][n]: 256 + 8
constexpr int ASTG = BM * AST;       // 9216 halves / stage
constexpr int BSTG = BN * B0ST;      // 18432 halves / stage (>= 64*264 = 16896)
constexpr int SMEM_BYTES = 2 * (ASTG + BSTG) * 2;   // 110592 B

__device__ __forceinline__ uint32_t s2u(const void* p) {
    uint32_t a;
    asm("{ .reg .u64 t; cvta.to.shared.u64 t, %1; cvt.u32.u64 %0, t; }"
        : "=r"(a) : "l"(p));
    return a;
}
__device__ __forceinline__ void cp16(uint32_t s, const void* g) {
    asm volatile("cp.async.cg.shared.global [%0], [%1], 16;\n" :: "r"(s), "l"(g));
}

template<int BLAYOUT>
__device__ __forceinline__ void load_tile(
    const __half* __restrict__ A, const __half* __restrict__ B,
    int K, int N, int m0, int n0, int tid,
    uint32_t as_u, uint32_t bs_u, int buf, int k0)
{
#pragma unroll
    for (int p = 0; p < 2; p++) {                 // A: 128x64 halves = 1024 x 16B
        const int c = tid + p * 512;
        const int row = c >> 3, k8 = (c & 7) * 8;
        cp16(as_u + (buf * ASTG + row * AST + k8) * 2,
             A + (long)(m0 + row) * K + k0 + k8);
    }
#pragma unroll
    for (int p = 0; p < 4; p++) {                 // B: 2048 x 16B
        const int c = tid + p * 512;
        if (BLAYOUT == 0) {
            const int row = c >> 3, k8 = (c & 7) * 8;
            cp16(bs_u + (buf * BSTG + row * B0ST + k8) * 2,
                 B + (long)(n0 + row) * K + k0 + k8);
        } else {
            const int row = c >> 5, n8 = (c & 31) * 8;
            cp16(bs_u + (buf * BSTG + row * B1ST + n8) * 2,
                 B + (long)(k0 + row) * N + n0 + n8);
        }
    }
}

template<int BLAYOUT, int OUTF32>
__global__ void __launch_bounds__(512, 1)
hgemm(const __half* __restrict__ A, const __half* __restrict__ B,
      void* __restrict__ Cv,
      int M, int N, int K, long sA, long sB, long sC,
      const float* __restrict__ bias, float scale)
{
    extern __shared__ __half sm[];
    const uint32_t as_u = s2u(sm);
    const uint32_t bs_u = s2u(sm + 2 * ASTG);

    A += (long)blockIdx.z * sA;
    B += (long)blockIdx.z * sB;

    const int m0 = blockIdx.y * BM;
    const int n0 = blockIdx.x * BN;
    const int tid = threadIdx.x;
    const int lane = tid & 31;
    const int warp = tid >> 5;
    const int wm = (warp & 3) * 32;    // 4 warps over M
    const int wn = (warp >> 2) * 64;   // 4 warps over N

    // ldmatrix per-lane bases (halves)
    const int lhi = lane >> 4;                       // 0/1
    const int a_off = (wm + (lane & 15)) * AST + lhi * 8;
    int b_off;
    if (BLAYOUT == 0)
        b_off = (wn + (lane & 7) + lhi * 8) * B0ST + ((lane >> 3) & 1) * 8;
    else
        b_off = (((lane >> 3) & 1) * 8 + (lane & 7)) * B1ST + wn + lhi * 8;

    float acc[2][8][4];
#pragma unroll
    for (int i = 0; i < 2; i++)
#pragma unroll
        for (int j = 0; j < 8; j++)
#pragma unroll
            for (int c = 0; c < 4; c++) acc[i][j][c] = 0.f;

    load_tile<BLAYOUT>(A, B, K, N, m0, n0, tid, as_u, bs_u, 0, 0);
    asm volatile("cp.async.commit_group;\n");

    const int nt = K / BK;
    for (int t = 0; t < nt; t++) {
        const int buf = t & 1;
        if (t + 1 < nt) {
            load_tile<BLAYOUT>(A, B, K, N, m0, n0, tid, as_u, bs_u, buf ^ 1, (t + 1) * BK);
            asm volatile("cp.async.commit_group;\n");
            asm volatile("cp.async.wait_group 1;\n");
        } else {
            asm volatile("cp.async.wait_group 0;\n");
        }
        __syncthreads();

#pragma unroll
        for (int kk = 0; kk < BK; kk += 16) {
            uint32_t a[2][4];
#pragma unroll
            for (int i = 0; i < 2; i++) {
                const uint32_t addr =
                    as_u + (buf * ASTG + a_off + i * (16 * AST) + kk) * 2;
                asm volatile(
                    "ldmatrix.sync.aligned.m8n8.x4.shared.b16 {%0,%1,%2,%3}, [%4];"
                    : "=r"(a[i][0]), "=r"(a[i][1]), "=r"(a[i][2]), "=r"(a[i][3])
                    : "r"(addr));
            }
            uint32_t b[8][2];
#pragma unroll
            for (int jp = 0; jp < 4; jp++) {
                if (BLAYOUT == 0) {
                    const uint32_t addr =
                        bs_u + (buf * BSTG + b_off + jp * (16 * B0ST) + kk) * 2;
                    asm volatile(
                        "ldmatrix.sync.aligned.m8n8.x4.shared.b16 {%0,%1,%2,%3}, [%4];"
                        : "=r"(b[2*jp][0]), "=r"(b[2*jp][1]),
                          "=r"(b[2*jp+1][0]), "=r"(b[2*jp+1][1])
                        : "r"(addr));
                } else {
                    const uint32_t addr =
                        bs_u + (buf * BSTG + b_off + jp * 16 + kk * B1ST) * 2;
                    asm volatile(
                        "ldmatrix.sync.aligned.m8n8.x4.trans.shared.b16 {%0,%1,%2,%3}, [%4];"
                        : "=r"(b[2*jp][0]), "=r"(b[2*jp][1]),
                          "=r"(b[2*jp+1][0]), "=r"(b[2*jp+1][1])
                        : "r"(addr));
                }
            }
#pragma unroll
            for (int i = 0; i < 2; i++)
#pragma unroll
                for (int j = 0; j < 8; j++)
                    asm volatile(
                        "mma.sync.aligned.m16n8k16.row.col.f32.f16.f16.f32 "
                        "{%0,%1,%2,%3}, {%4,%5,%6,%7}, {%8,%9}, {%0,%1,%2,%3};\n"
                        : "+f"(acc[i][j][0]), "+f"(acc[i][j][1]),
                          "+f"(acc[i][j][2]), "+f"(acc[i][j][3])
                        : "r"(a[i][0]), "r"(a[i][1]), "r"(a[i][2]), "r"(a[i][3]),
                          "r"(b[j][0]), "r"(b[j][1]));
        }
        __syncthreads();
    }

    // ---- epilogue ----
    const int g = lane >> 2, tq = lane & 3;
#pragma unroll
    for (int i = 0; i < 2; i++) {
        const int r0 = m0 + wm + i * 16 + g;
#pragma unroll
        for (int j = 0; j < 8; j++) {
            const int col = n0 + wn + j * 8 + 2 * tq;
            float b0 = 0.f, b1 = 0.f;
            if (bias) { b0 = bias[col]; b1 = bias[col + 1]; }
            const float c0 = acc[i][j][0] * scale + b0;
            const float c1 = acc[i][j][1] * scale + b1;
            const float c2 = acc[i][j][2] * scale + b0;
            const float c3 = acc[i][j][3] * scale + b1;
            if (OUTF32) {
                float* C = (float*)Cv + (long)blockIdx.z * sC;
                *reinterpret_cast<float2*>(C + (long)r0 * N + col) = make_float2(c0, c1);
                *reinterpret_cast<float2*>(C + (long)(r0 + 8) * N + col) = make_float2(c2, c3);
            } else {
                __half* C = (__half*)Cv + (long)blockIdx.z * sC;
                *reinterpret_cast<__half2*>(C + (long)r0 * N + col) = __floats2half2_rn(c0, c1);
                *reinterpret_cast<__half2*>(C + (long)(r0 + 8) * N + col) = __floats2half2_rn(c2, c3);
            }
        }
    }
}

// ---------------- fp16 in-place row softmax (fp32 math) ---------------------
__global__ void __launch_bounds__(256)
softmax_h(__half* __restrict__ Sm)
{
    const long row = blockIdx.x;
    __half* p = Sm + row * (long)S_LEN;
    const int tid = threadIdx.x;

    uint4 u0 = reinterpret_cast<uint4*>(p)[tid];
    uint4 u1 = reinterpret_cast<uint4*>(p)[tid + 256];
    uint32_t w[8] = {u0.x, u0.y, u0.z, u0.w, u1.x, u1.y, u1.z, u1.w};
    float f[16];
    float mx = -3.0e38f;
#pragma unroll
    for (int i = 0; i < 8; i++) {
        float2 v = __half22float2(*reinterpret_cast<__half2*>(&w[i]));
        f[2*i] = v.x; f[2*i+1] = v.y;
        mx = fmaxf(mx, fmaxf(v.x, v.y));
    }
    __shared__ float red[8];
#pragma unroll
    for (int o = 16; o; o >>= 1) mx = fmaxf(mx, __shfl_xor_sync(0xffffffffu, mx, o));
    if ((tid & 31) == 0) red[tid >> 5] = mx;
    __syncthreads();
    mx = red[0];
#pragma unroll
    for (int k = 1; k < 8; k++) mx = fmaxf(mx, red[k]);
    __syncthreads();

    float sum = 0.f;
#pragma unroll
    for (int i = 0; i < 16; i++) { f[i] = __expf(f[i] - mx); sum += f[i]; }
#pragma unroll
    for (int o = 16; o; o >>= 1) sum += __shfl_xor_sync(0xffffffffu, sum, o);
    if ((tid & 31) == 0) red[tid >> 5] = sum;
    __syncthreads();
    sum = 0.f;
#pragma unroll
    for (int k = 0; k < 8; k++) sum += red[k];
    const float inv = 1.0f / sum;

#pragma unroll
    for (int i = 0; i < 8; i++)
        *reinterpret_cast<__half2*>(&w[i]) = __floats2half2_rn(f[2*i] * inv, f[2*i+1] * inv);
    reinterpret_cast<uint4*>(p)[tid]       = make_uint4(w[0], w[1], w[2], w[3]);
    reinterpret_cast<uint4*>(p)[tid + 256] = make_uint4(w[4], w[5], w[6], w[7]);
}

// ---------------- launch ------------------------------------------------------
extern "C" void kernel_launch(void* const* d_in, const int* in_sizes, int n_in,
                              void* d_out, int out_size)
{
    const float* x  = (const float*)d_in[0];
    const float* Wq = (const float*)d_in[1];
    const float* bq = (const float*)d_in[2];
    const float* Wk = (const float*)d_in[3];
    const float* bk = (const float*)d_in[4];
    const float* Wv = (const float*)d_in[5];
    const float* bv = (const float*)d_in[6];
    const float* Wo = (const float*)d_in[7];
    const float* bo = (const float*)d_in[8];
    float* out = (float*)d_out;

    __half *xh, *wq, *wk, *wv, *wo, *Qh, *Kh, *Vh, *Sh, *Ch;
    cudaGetSymbolAddress((void**)&xh, g_xh);
    cudaGetSymbolAddress((void**)&wq, g_wq);
    cudaGetSymbolAddress((void**)&wk, g_wk);
    cudaGetSymbolAddress((void**)&wv, g_wv);
    cudaGetSymbolAddress((void**)&wo, g_wo);
    cudaGetSymbolAddress((void**)&Qh, g_Qh);
    cudaGetSymbolAddress((void**)&Kh, g_Kh);
    cudaGetSymbolAddress((void**)&Vh, g_Vh);
    cudaGetSymbolAddress((void**)&Sh, g_Sh);
    cudaGetSymbolAddress((void**)&Ch, g_Ch);

    cudaFuncSetAttribute(hgemm<0,0>, cudaFuncAttributeMaxDynamicSharedMemorySize, SMEM_BYTES);
    cudaFuncSetAttribute(hgemm<1,0>, cudaFuncAttributeMaxDynamicSharedMemorySize, SMEM_BYTES);
    cudaFuncSetAttribute(hgemm<0,1>, cudaFuncAttributeMaxDynamicSharedMemorySize, SMEM_BYTES);

    // 0) fp32 -> fp16 conversions
    cvt_f2h<<<(MROWS * DIM) / 1024, 256>>>(x,  xh);
    cvt_f2h<<<(DIM * DIM)   / 1024, 256>>>(Wq, wq);
    cvt_f2h<<<(DIM * DIM)   / 1024, 256>>>(Wk, wk);
    cvt_f2h<<<(DIM * DIM)   / 1024, 256>>>(Wv, wv);
    cvt_f2h<<<(DIM * DIM)   / 1024, 256>>>(Wo, wo);

    dim3 blk(512);

    // 1) QKV projections
    dim3 gq(DIM / BN, MROWS / BM, 1);
    hgemm<0,0><<<gq, blk, SMEM_BYTES>>>(xh, wq, Qh, MROWS, DIM, DIM, 0, 0, 0, bq, 1.f);
    hgemm<0,0><<<gq, blk, SMEM_BYTES>>>(xh, wk, Kh, MROWS, DIM, DIM, 0, 0, 0, bk, 1.f);
    hgemm<0,0><<<gq, blk, SMEM_BYTES>>>(xh, wv, Vh, MROWS, DIM, DIM, 0, 0, 0, bv, 1.f);

    // 2) scores = Q @ K^T / 32
    dim3 gs(S_LEN / BN, S_LEN / BM, BATCH);
    hgemm<0,0><<<gs, blk, SMEM_BYTES>>>(Qh, Kh, Sh, S_LEN, S_LEN, DIM,
                                        (long)S_LEN * DIM, (long)S_LEN * DIM,
                                        (long)S_LEN * S_LEN, nullptr, 0.03125f);

    // 3) softmax
    softmax_h<<<MROWS, 256>>>(Sh);

    // 4) ctx = P @ V
    dim3 gc(DIM / BN, S_LEN / BM, BATCH);
    hgemm<1,0><<<gc, blk, SMEM_BYTES>>>(Sh, Vh, Ch, S_LEN, DIM, S_LEN,
                                        (long)S_LEN * S_LEN, (long)S_LEN * DIM,
                                        (long)S_LEN * DIM, nullptr, 1.f);

    // 5) out = ctx @ Wo^T + bo
    hgemm<0,1><<<gq, blk, SMEM_BYTES>>>(Ch, wo, out, MROWS, DIM, DIM, 0, 0, 0, bo, 1.f);
}

// round 13
// speedup vs baseline: 2.5976x; 1.1011x over previous
#include <cuda_runtime.h>
#include <cuda_fp16.h>
#include <cstdint>

#define S_LEN 4096
#define BATCH 4
#define DIM   1024
#define MROWS (BATCH * S_LEN)   // 16384

// ---------------- scratch (allocation-free __device__ globals) --------------
__device__ __half g_xh[(size_t)MROWS * DIM];
__device__ __half g_wqkv[(size_t)3 * DIM * DIM];     // packed [3072, 1024]
__device__ __half g_wo[(size_t)DIM * DIM];
__device__ float  g_bqkv[3 * DIM];
__device__ __half g_QKV[(size_t)MROWS * 3 * DIM];    // packed [16384, 3072]
__device__ __half g_Sh[(size_t)BATCH * S_LEN * S_LEN];
__device__ __half g_Ch[(size_t)MROWS * DIM];

// ---------------- fp32 -> fp16 converter ------------------------------------
__global__ void __launch_bounds__(256)
cvt_f2h(const float* __restrict__ in, __half* __restrict__ out)
{
    const long i = ((long)blockIdx.x * 256 + threadIdx.x) * 4;
    float4 v = *reinterpret_cast<const float4*>(in + i);
    __half2* o = reinterpret_cast<__half2*>(out + i);
    o[0] = __floats2half2_rn(v.x, v.y);
    o[1] = __floats2half2_rn(v.z, v.w);
}

// ---------------- fp16 GEMM --------------------------------------------------
// C[M,N] = scale * (A @ opB) + bias
//   BLAYOUT==0 : B is [N,K] rows (ldB) -> C = A @ B^T
//   BLAYOUT==1 : B is [K,N] rows (ldB) -> C = A @ B      (ldmatrix.trans)
// BM=128, BN=256, BK=64; 512 threads = 16 warps (4M x 4N), warp tile 32x64,
// m16n8k16 HMMA fp32-acc, 3-stage cp.async pipeline, 1 barrier per K-iter.
constexpr int BM = 128, BN = 256, BK = 64;
constexpr int STG = 3;
constexpr int AST  = 72;             // A smem stride (halves): 64 + 8
constexpr int B0ST = 72;             // B smem stride, layout0 [n][k]
constexpr int B1ST = 264;            // B smem stride, layout1 [k][n]
constexpr int ASTG = BM * AST;       // 9216 halves / stage
constexpr int BSTG = BN * B0ST;      // 18432 halves / stage (>= 64*264)
constexpr int SMEM_BYTES = STG * (ASTG + BSTG) * 2;   // 165888 B

__device__ __forceinline__ uint32_t s2u(const void* p) {
    uint32_t a;
    asm("{ .reg .u64 t; cvta.to.shared.u64 t, %1; cvt.u32.u64 %0, t; }"
        : "=r"(a) : "l"(p));
    return a;
}
__device__ __forceinline__ void cp16(uint32_t s, const void* g) {
    asm volatile("cp.async.cg.shared.global [%0], [%1], 16;\n" :: "r"(s), "l"(g));
}

template<int BLAYOUT>
__device__ __forceinline__ void load_tile(
    const __half* __restrict__ A, const __half* __restrict__ B,
    int ldA, int ldB, int m0, int n0, int tid,
    uint32_t as_u, uint32_t bs_u, int buf, int k0)
{
#pragma unroll
    for (int p = 0; p < 2; p++) {                 // A: 128x64 halves = 1024 x 16B
        const int c = tid + p * 512;
        const int row = c >> 3, k8 = (c & 7) * 8;
        cp16(as_u + (buf * ASTG + row * AST + k8) * 2,
             A + (long)(m0 + row) * ldA + k0 + k8);
    }
#pragma unroll
    for (int p = 0; p < 4; p++) {                 // B: 2048 x 16B
        const int c = tid + p * 512;
        if (BLAYOUT == 0) {
            const int row = c >> 3, k8 = (c & 7) * 8;
            cp16(bs_u + (buf * BSTG + row * B0ST + k8) * 2,
                 B + (long)(n0 + row) * ldB + k0 + k8);
        } else {
            const int row = c >> 5, n8 = (c & 31) * 8;
            cp16(bs_u + (buf * BSTG + row * B1ST + n8) * 2,
                 B + (long)(k0 + row) * ldB + n0 + n8);
        }
    }
}

template<int BLAYOUT, int OUTF32>
__global__ void __launch_bounds__(512, 1)
hgemm(const __half* __restrict__ A, const __half* __restrict__ B,
      void* __restrict__ Cv,
      int K, int ldA, int ldB, int ldC,
      long sA, long sB, long sC,
      const float* __restrict__ bias, float scale)
{
    extern __shared__ __half sm[];
    const uint32_t as_u = s2u(sm);
    const uint32_t bs_u = s2u(sm + STG * ASTG);

    A += (long)blockIdx.z * sA;
    B += (long)blockIdx.z * sB;

    const int m0 = blockIdx.y * BM;
    const int n0 = blockIdx.x * BN;
    const int tid = threadIdx.x;
    const int lane = tid & 31;
    const int warp = tid >> 5;
    const int wm = (warp & 3) * 32;    // 4 warps over M
    const int wn = (warp >> 2) * 64;   // 4 warps over N

    // ldmatrix per-lane bases (halves)
    const int lhi = lane >> 4;                       // 0/1
    const int a_off = (wm + (lane & 15)) * AST + lhi * 8;
    int b_off;
    if (BLAYOUT == 0)
        b_off = (wn + (lane & 7) + lhi * 8) * B0ST + ((lane >> 3) & 1) * 8;
    else
        b_off = (((lane >> 3) & 1) * 8 + (lane & 7)) * B1ST + wn + lhi * 8;

    float acc[2][8][4];
#pragma unroll
    for (int i = 0; i < 2; i++)
#pragma unroll
        for (int j = 0; j < 8; j++)
#pragma unroll
            for (int c = 0; c < 4; c++) acc[i][j][c] = 0.f;

    const int nt = K / BK;
    load_tile<BLAYOUT>(A, B, ldA, ldB, m0, n0, tid, as_u, bs_u, 0, 0);
    asm volatile("cp.async.commit_group;\n");
    load_tile<BLAYOUT>(A, B, ldA, ldB, m0, n0, tid, as_u, bs_u, 1, BK);
    asm volatile("cp.async.commit_group;\n");

    int buf = 0;
    for (int t = 0; t < nt; t++) {
        if (t + 1 < nt)
            asm volatile("cp.async.wait_group 1;\n");
        else
            asm volatile("cp.async.wait_group 0;\n");
        __syncthreads();

        if (t + 2 < nt) {
            int nb = buf + 2; if (nb >= STG) nb -= STG;
            load_tile<BLAYOUT>(A, B, ldA, ldB, m0, n0, tid, as_u, bs_u, nb, (t + 2) * BK);
            asm volatile("cp.async.commit_group;\n");
        }

#pragma unroll
        for (int kk = 0; kk < BK; kk += 16) {
            uint32_t a[2][4];
#pragma unroll
            for (int i = 0; i < 2; i++) {
                const uint32_t addr =
                    as_u + (buf * ASTG + a_off + i * (16 * AST) + kk) * 2;
                asm volatile(
                    "ldmatrix.sync.aligned.m8n8.x4.shared.b16 {%0,%1,%2,%3}, [%4];"
                    : "=r"(a[i][0]), "=r"(a[i][1]), "=r"(a[i][2]), "=r"(a[i][3])
                    : "r"(addr));
            }
            uint32_t b[8][2];
#pragma unroll
            for (int jp = 0; jp < 4; jp++) {
                if (BLAYOUT == 0) {
                    const uint32_t addr =
                        bs_u + (buf * BSTG + b_off + jp * (16 * B0ST) + kk) * 2;
                    asm volatile(
                        "ldmatrix.sync.aligned.m8n8.x4.shared.b16 {%0,%1,%2,%3}, [%4];"
                        : "=r"(b[2*jp][0]), "=r"(b[2*jp][1]),
                          "=r"(b[2*jp+1][0]), "=r"(b[2*jp+1][1])
                        : "r"(addr));
                } else {
                    const uint32_t addr =
                        bs_u + (buf * BSTG + b_off + jp * 16 + kk * B1ST) * 2;
                    asm volatile(
                        "ldmatrix.sync.aligned.m8n8.x4.trans.shared.b16 {%0,%1,%2,%3}, [%4];"
                        : "=r"(b[2*jp][0]), "=r"(b[2*jp][1]),
                          "=r"(b[2*jp+1][0]), "=r"(b[2*jp+1][1])
                        : "r"(addr));
                }
            }
#pragma unroll
            for (int i = 0; i < 2; i++)
#pragma unroll
                for (int j = 0; j < 8; j++)
                    asm volatile(
                        "mma.sync.aligned.m16n8k16.row.col.f32.f16.f16.f32 "
                        "{%0,%1,%2,%3}, {%4,%5,%6,%7}, {%8,%9}, {%0,%1,%2,%3};\n"
                        : "+f"(acc[i][j][0]), "+f"(acc[i][j][1]),
                          "+f"(acc[i][j][2]), "+f"(acc[i][j][3])
                        : "r"(a[i][0]), "r"(a[i][1]), "r"(a[i][2]), "r"(a[i][3]),
                          "r"(b[j][0]), "r"(b[j][1]));
        }
        buf++; if (buf >= STG) buf -= STG;
    }

    // ---- epilogue ----
    const int g = lane >> 2, tq = lane & 3;
#pragma unroll
    for (int i = 0; i < 2; i++) {
        const int r0 = m0 + wm + i * 16 + g;
#pragma unroll
        for (int j = 0; j < 8; j++) {
            const int col = n0 + wn + j * 8 + 2 * tq;
            float b0 = 0.f, b1 = 0.f;
            if (bias) { b0 = bias[col]; b1 = bias[col + 1]; }
            const float c0 = acc[i][j][0] * scale + b0;
            const float c1 = acc[i][j][1] * scale + b1;
            const float c2 = acc[i][j][2] * scale + b0;
            const float c3 = acc[i][j][3] * scale + b1;
            if (OUTF32) {
                float* C = (float*)Cv + (long)blockIdx.z * sC;
                *reinterpret_cast<float2*>(C + (long)r0 * ldC + col) = make_float2(c0, c1);
                *reinterpret_cast<float2*>(C + (long)(r0 + 8) * ldC + col) = make_float2(c2, c3);
            } else {
                __half* C = (__half*)Cv + (long)blockIdx.z * sC;
                *reinterpret_cast<__half2*>(C + (long)r0 * ldC + col) = __floats2half2_rn(c0, c1);
                *reinterpret_cast<__half2*>(C + (long)(r0 + 8) * ldC + col) = __floats2half2_rn(c2, c3);
            }
        }
    }
}

// ---------------- fp16 in-place row softmax (fp32 math) ---------------------
__global__ void __launch_bounds__(256)
softmax_h(__half* __restrict__ Sm)
{
    const long row = blockIdx.x;
    __half* p = Sm + row * (long)S_LEN;
    const int tid = threadIdx.x;

    uint4 u0 = reinterpret_cast<uint4*>(p)[tid];
    uint4 u1 = reinterpret_cast<uint4*>(p)[tid + 256];
    uint32_t w[8] = {u0.x, u0.y, u0.z, u0.w, u1.x, u1.y, u1.z, u1.w};
    float f[16];
    float mx = -3.0e38f;
#pragma unroll
    for (int i = 0; i < 8; i++) {
        float2 v = __half22float2(*reinterpret_cast<__half2*>(&w[i]));
        f[2*i] = v.x; f[2*i+1] = v.y;
        mx = fmaxf(mx, fmaxf(v.x, v.y));
    }
    __shared__ float red[8];
#pragma unroll
    for (int o = 16; o; o >>= 1) mx = fmaxf(mx, __shfl_xor_sync(0xffffffffu, mx, o));
    if ((tid & 31) == 0) red[tid >> 5] = mx;
    __syncthreads();
    mx = red[0];
#pragma unroll
    for (int k = 1; k < 8; k++) mx = fmaxf(mx, red[k]);
    __syncthreads();

    float sum = 0.f;
#pragma unroll
    for (int i = 0; i < 16; i++) { f[i] = __expf(f[i] - mx); sum += f[i]; }
#pragma unroll
    for (int o = 16; o; o >>= 1) sum += __shfl_xor_sync(0xffffffffu, sum, o);
    if ((tid & 31) == 0) red[tid >> 5] = sum;
    __syncthreads();
    sum = 0.f;
#pragma unroll
    for (int k = 0; k < 8; k++) sum += red[k];
    const float inv = 1.0f / sum;

#pragma unroll
    for (int i = 0; i < 8; i++)
        *reinterpret_cast<__half2*>(&w[i]) = __floats2half2_rn(f[2*i] * inv, f[2*i+1] * inv);
    reinterpret_cast<uint4*>(p)[tid]       = make_uint4(w[0], w[1], w[2], w[3]);
    reinterpret_cast<uint4*>(p)[tid + 256] = make_uint4(w[4], w[5], w[6], w[7]);
}

// ---------------- launch ------------------------------------------------------
extern "C" void kernel_launch(void* const* d_in, const int* in_sizes, int n_in,
                              void* d_out, int out_size)
{
    const float* x  = (const float*)d_in[0];
    const float* Wq = (const float*)d_in[1];
    const float* bq = (const float*)d_in[2];
    const float* Wk = (const float*)d_in[3];
    const float* bk = (const float*)d_in[4];
    const float* Wv = (const float*)d_in[5];
    const float* bv = (const float*)d_in[6];
    const float* Wo = (const float*)d_in[7];
    const float* bo = (const float*)d_in[8];
    float* out = (float*)d_out;

    __half *xh, *wqkv, *wo, *QKV, *Sh, *Ch;
    float* bqkv;
    cudaGetSymbolAddress((void**)&xh,   g_xh);
    cudaGetSymbolAddress((void**)&wqkv, g_wqkv);
    cudaGetSymbolAddress((void**)&wo,   g_wo);
    cudaGetSymbolAddress((void**)&bqkv, g_bqkv);
    cudaGetSymbolAddress((void**)&QKV,  g_QKV);
    cudaGetSymbolAddress((void**)&Sh,   g_Sh);
    cudaGetSymbolAddress((void**)&Ch,   g_Ch);

    cudaFuncSetAttribute(hgemm<0,0>, cudaFuncAttributeMaxDynamicSharedMemorySize, SMEM_BYTES);
    cudaFuncSetAttribute(hgemm<1,0>, cudaFuncAttributeMaxDynamicSharedMemorySize, SMEM_BYTES);
    cudaFuncSetAttribute(hgemm<0,1>, cudaFuncAttributeMaxDynamicSharedMemorySize, SMEM_BYTES);

    // 0) pack fp16 operands + biases
    cvt_f2h<<<(MROWS * DIM) / 1024, 256>>>(x,  xh);
    cvt_f2h<<<(DIM * DIM)   / 1024, 256>>>(Wq, wqkv);
    cvt_f2h<<<(DIM * DIM)   / 1024, 256>>>(Wk, wqkv + (size_t)DIM * DIM);
    cvt_f2h<<<(DIM * DIM)   / 1024, 256>>>(Wv, wqkv + (size_t)2 * DIM * DIM);
    cvt_f2h<<<(DIM * DIM)   / 1024, 256>>>(Wo, wo);
    cudaMemcpyAsync(bqkv,            bq, DIM * sizeof(float), cudaMemcpyDeviceToDevice);
    cudaMemcpyAsync(bqkv + DIM,      bk, DIM * sizeof(float), cudaMemcpyDeviceToDevice);
    cudaMemcpyAsync(bqkv + 2 * DIM,  bv, DIM * sizeof(float), cudaMemcpyDeviceToDevice);

    dim3 blk(512);
    const __half* Qp = QKV;
    const __half* Kp = QKV + DIM;
    const __half* Vp = QKV + 2 * DIM;

    // 1) fused QKV: [16384,1024] @ [3072,1024]^T -> packed [16384,3072]
    hgemm<0,0><<<dim3(3 * DIM / BN, MROWS / BM, 1), blk, SMEM_BYTES>>>(
        xh, wqkv, QKV, DIM, DIM, DIM, 3 * DIM, 0, 0, 0, bqkv, 1.f);

    // 2) scores = Q @ K^T / 32, batched
    hgemm<0,0><<<dim3(S_LEN / BN, S_LEN / BM, BATCH), blk, SMEM_BYTES>>>(
        Qp, Kp, Sh, DIM, 3 * DIM, 3 * DIM, S_LEN,
        (long)S_LEN * 3 * DIM, (long)S_LEN * 3 * DIM, (long)S_LEN * S_LEN,
        nullptr, 0.03125f);

    // 3) softmax
    softmax_h<<<MROWS, 256>>>(Sh);

    // 4) ctx = P @ V (layout1: B rows are K)
    hgemm<1,0><<<dim3(DIM / BN, S_LEN / BM, BATCH), blk, SMEM_BYTES>>>(
        Sh, Vp, Ch, S_LEN, S_LEN, 3 * DIM, DIM,
        (long)S_LEN * S_LEN, (long)S_LEN * 3 * DIM, (long)S_LEN * DIM,
        nullptr, 1.f);

    // 5) out = ctx @ Wo^T + bo (fp32 out)
    hgemm<0,1><<<dim3(DIM / BN, MROWS / BM, 1), blk, SMEM_BYTES>>>(
        Ch, wo, out, DIM, DIM, DIM, DIM, 0, 0, 0, bo, 1.f);
}